// round 2
// baseline (speedup 1.0000x reference)
#include <cuda_runtime.h>
#include <math.h>

// ---------------- constants ----------------
#define BATCH 4096
#define NR 512          // routes
#define RI 4096         // routes*8
#define OD 64           // 2 caps * 32 dims
#define OUT_V_OFF 0
#define OUT_REC_OFF 262144
#define OUT_MASK_OFF 524288

// ---------------- scratch (device globals; no cudaMalloc allowed) ----------------
__device__ float g_wT[256 * 9 * 64];            // prim_w transposed [ic][k9][oc]
__device__ float g_u[(size_t)BATCH * RI];       // squashed primary caps [B][512*8]  (64 MB)
__device__ float g_WcT[RI * OD];                // c[r,o]*W[r,o,d,i] laid out [ri][od]
__device__ float g_bij[NR * 2];
__device__ float g_c[NR * 2];
__device__ float g_s[BATCH * OD];
__device__ float g_v[BATCH * OD];
__device__ float g_G[RI * OD];
__device__ float g_h0[BATCH * 64];
__device__ float g_h1[BATCH * 512];
__device__ float g_h2[(size_t)BATCH * 1024];

// ---------------- helpers ----------------
__device__ __forceinline__ float warp_sum(float v) {
    #pragma unroll
    for (int s = 16; s > 0; s >>= 1) v += __shfl_xor_sync(0xFFFFFFFFu, v, s);
    return v;
}

// ---------------- kernel: zero buffer ----------------
__global__ void zero_kernel(float* p, int n) {
    int i = blockIdx.x * blockDim.x + threadIdx.x;
    if (i < n) p[i] = 0.0f;
}

// ---------------- kernel: transpose prim weights to [ic][k][oc] ----------------
__global__ void transpose_w_kernel(const float* __restrict__ pw) {
    int idx = blockIdx.x * blockDim.x + threadIdx.x;   // 147456
    if (idx >= 147456) return;
    int oc = idx / 2304;
    int rem = idx % 2304;
    int ic = rem / 9;
    int k = rem % 9;
    g_wT[ic * 576 + k * 64 + oc] = pw[idx];
}

// ---------------- kernel: fused conv1 + primary conv + squash ----------------
// one CTA per image, 256 threads
__global__ void __launch_bounds__(256, 2) conv_fused_kernel(
    const float* __restrict__ data, const float* __restrict__ w1,
    const float* __restrict__ b1, const float* __restrict__ pb)
{
    __shared__ float s_img[64];
    __shared__ float s_x[256][68];  // conv1 output, padded for bank spread / float4 align

    int b = blockIdx.x;
    int tid = threadIdx.x;

    if (tid < 64) s_img[tid] = data[b * 64 + tid];
    __syncthreads();

    // ---- phase 1: conv1 (3x3, pad 1) + relu; thread = input channel ic ----
    {
        int ic = tid;
        float w[9];
        #pragma unroll
        for (int k = 0; k < 9; k++) w[k] = w1[ic * 9 + k];
        float bias = b1[ic];
        #pragma unroll
        for (int y = 0; y < 8; y++) {
            #pragma unroll
            for (int x = 0; x < 8; x++) {
                float acc = bias;
                #pragma unroll
                for (int ky = 0; ky < 3; ky++) {
                    int iy = y + ky - 1;
                    if (iy < 0 || iy > 7) continue;
                    #pragma unroll
                    for (int kx = 0; kx < 3; kx++) {
                        int ix = x + kx - 1;
                        if (ix < 0 || ix > 7) continue;
                        acc += w[ky * 3 + kx] * s_img[iy * 8 + ix];
                    }
                }
                s_x[ic][y * 8 + x] = fmaxf(acc, 0.0f);
            }
        }
    }
    __syncthreads();

    // ---- phase 2: primary conv (64 oc, 256 ic, 3x3 pad1) ----
    // thread = (oc, row-pair t);   warp lanes share t -> x-tile reads broadcast,
    // weight reads coalesced along oc via g_wT layout.
    int oc = tid & 63;
    int t = tid >> 6;
    int y0 = t * 2;

    float bias = pb[oc];
    float acc0[8], acc1[8];
    #pragma unroll
    for (int j = 0; j < 8; j++) { acc0[j] = bias; acc1[j] = bias; }

    for (int ic = 0; ic < 256; ic++) {
        float xr[4][8];
        #pragma unroll
        for (int rr = 0; rr < 4; rr++) {
            int ry = y0 - 1 + rr;
            if (ry >= 0 && ry <= 7) {
                float4 p0 = *(const float4*)&s_x[ic][ry * 8];
                float4 p1 = *(const float4*)&s_x[ic][ry * 8 + 4];
                xr[rr][0] = p0.x; xr[rr][1] = p0.y; xr[rr][2] = p0.z; xr[rr][3] = p0.w;
                xr[rr][4] = p1.x; xr[rr][5] = p1.y; xr[rr][6] = p1.z; xr[rr][7] = p1.w;
            } else {
                #pragma unroll
                for (int j = 0; j < 8; j++) xr[rr][j] = 0.0f;
            }
        }
        const float* wp = g_wT + ic * 576 + oc;
        #pragma unroll
        for (int ky = 0; ky < 3; ky++) {
            #pragma unroll
            for (int kx = 0; kx < 3; kx++) {
                float w = wp[(ky * 3 + kx) * 64];
                #pragma unroll
                for (int xx = 0; xx < 8; xx++) {
                    int ix = xx + kx - 1;
                    if (ix >= 0 && ix <= 7) {
                        acc0[xx] += w * xr[ky][ix];
                        acc1[xx] += w * xr[ky + 1][ix];
                    }
                }
            }
        }
    }

    // ---- squash each 8-vector (route = oc*8 + row, dim = x) and store ----
    {
        float* base = g_u + (size_t)b * RI;
        float sq0 = 0.0f, sq1 = 0.0f;
        #pragma unroll
        for (int j = 0; j < 8; j++) { sq0 += acc0[j] * acc0[j]; sq1 += acc1[j] * acc1[j]; }
        float sc0 = sq0 / ((1.0f + sq0) * sqrtf(sq0 + 1e-9f));
        float sc1 = sq1 / ((1.0f + sq1) * sqrtf(sq1 + 1e-9f));
        float4 v0a = make_float4(acc0[0]*sc0, acc0[1]*sc0, acc0[2]*sc0, acc0[3]*sc0);
        float4 v0b = make_float4(acc0[4]*sc0, acc0[5]*sc0, acc0[6]*sc0, acc0[7]*sc0);
        float4 v1a = make_float4(acc1[0]*sc1, acc1[1]*sc1, acc1[2]*sc1, acc1[3]*sc1);
        float4 v1b = make_float4(acc1[4]*sc1, acc1[5]*sc1, acc1[6]*sc1, acc1[7]*sc1);
        float* d0 = base + (oc * 8 + y0) * 8;
        float* d1 = base + (oc * 8 + y0 + 1) * 8;
        *(float4*)(d0)     = v0a;  *(float4*)(d0 + 4) = v0b;
        *(float4*)(d1)     = v1a;  *(float4*)(d1 + 4) = v1b;
    }
}

// ---------------- kernel: softmax of b over routes (axis 0) ----------------
__global__ void softmax_routes_kernel() {
    __shared__ float red[512];
    int t = threadIdx.x;  // 512 threads
    for (int o = 0; o < 2; o++) {
        float val = g_bij[t * 2 + o];
        red[t] = val; __syncthreads();
        for (int s = 256; s > 0; s >>= 1) {
            if (t < s) red[t] = fmaxf(red[t], red[t + s]);
            __syncthreads();
        }
        float mx = red[0]; __syncthreads();
        float e = expf(val - mx);
        red[t] = e; __syncthreads();
        for (int s = 256; s > 0; s >>= 1) {
            if (t < s) red[t] += red[t + s];
            __syncthreads();
        }
        float sum = red[0]; __syncthreads();
        g_c[t * 2 + o] = e / sum;
    }
}

// ---------------- kernel: build WcT[ri][od] = c[r,o] * W[r,o,d,i] ----------------
__global__ void build_wct_kernel(const float* __restrict__ W) {
    int idx = blockIdx.x * blockDim.x + threadIdx.x;   // 262144
    if (idx >= RI * OD) return;
    int od = idx & 63, ri = idx >> 6;
    int r = ri >> 3, i = ri & 7, o = od >> 5, d = od & 31;
    g_WcT[idx] = g_c[r * 2 + o] * W[((r * 2 + o) * 32 + d) * 8 + i];
}

// ---------------- GEMM: C = act(A*B + bias);  A[MxK] rm, B[KxN] rm ----------------
__global__ void __launch_bounds__(256) gemm_ab_kernel(
    const float* __restrict__ A, const float* __restrict__ B,
    const float* __restrict__ bias, float* __restrict__ C,
    int M, int N, int K, int act)
{
    __shared__ float As[16][68];
    __shared__ float Bs[16][64];
    int tid = threadIdx.x;
    int n0 = blockIdx.x * 64, m0 = blockIdx.y * 64;
    int tx = tid & 15, ty = tid >> 4;
    float acc[4][4] = {};

    for (int k0 = 0; k0 < K; k0 += 16) {
        #pragma unroll
        for (int l = 0; l < 4; l++) {
            int lin = tid + l * 256;
            int kk = lin & 15, m = lin >> 4;
            As[kk][m] = A[(size_t)(m0 + m) * K + k0 + kk];
            int n = lin & 63, kb = lin >> 6;
            Bs[kb][n] = B[(size_t)(k0 + kb) * N + n0 + n];
        }
        __syncthreads();
        #pragma unroll
        for (int kk = 0; kk < 16; kk++) {
            float4 a = *(const float4*)&As[kk][ty * 4];
            float4 bv = *(const float4*)&Bs[kk][tx * 4];
            float av[4] = {a.x, a.y, a.z, a.w};
            float bb[4] = {bv.x, bv.y, bv.z, bv.w};
            #pragma unroll
            for (int i = 0; i < 4; i++)
                #pragma unroll
                for (int j = 0; j < 4; j++) acc[i][j] += av[i] * bb[j];
        }
        __syncthreads();
    }

    #pragma unroll
    for (int i = 0; i < 4; i++) {
        int m = m0 + ty * 4 + i;
        #pragma unroll
        for (int j = 0; j < 4; j++) {
            int n = n0 + tx * 4 + j;
            float v = acc[i][j] + (bias ? bias[n] : 0.0f);
            if (act == 1) v = fmaxf(v, 0.0f);
            else if (act == 2) v = 1.0f / (1.0f + expf(-v));
            C[(size_t)m * N + n] = v;
        }
    }
}

// ---------------- GEMM split-K (atomic): C += A*B   A[Mxlda] rm ----------------
__global__ void __launch_bounds__(256) gemm_ab_splitk_kernel(
    const float* __restrict__ A, const float* __restrict__ B, float* __restrict__ C,
    int M, int N, int lda, int Kchunk)
{
    __shared__ float As[16][68];
    __shared__ float Bs[16][64];
    int tid = threadIdx.x;
    int n0 = blockIdx.x * 64, m0 = blockIdx.y * 64;
    int kbase = blockIdx.z * Kchunk;
    int tx = tid & 15, ty = tid >> 4;
    float acc[4][4] = {};

    for (int k0 = 0; k0 < Kchunk; k0 += 16) {
        #pragma unroll
        for (int l = 0; l < 4; l++) {
            int lin = tid + l * 256;
            int kk = lin & 15, m = lin >> 4;
            As[kk][m] = A[(size_t)(m0 + m) * lda + kbase + k0 + kk];
            int n = lin & 63, kb = lin >> 6;
            Bs[kb][n] = B[(size_t)(kbase + k0 + kb) * N + n0 + n];
        }
        __syncthreads();
        #pragma unroll
        for (int kk = 0; kk < 16; kk++) {
            float4 a = *(const float4*)&As[kk][ty * 4];
            float4 bv = *(const float4*)&Bs[kk][tx * 4];
            float av[4] = {a.x, a.y, a.z, a.w};
            float bb[4] = {bv.x, bv.y, bv.z, bv.w};
            #pragma unroll
            for (int i = 0; i < 4; i++)
                #pragma unroll
                for (int j = 0; j < 4; j++) acc[i][j] += av[i] * bb[j];
        }
        __syncthreads();
    }
    #pragma unroll
    for (int i = 0; i < 4; i++) {
        int m = m0 + ty * 4 + i;
        #pragma unroll
        for (int j = 0; j < 4; j++) {
            int n = n0 + tx * 4 + j;
            atomicAdd(&C[(size_t)m * N + n], acc[i][j]);
        }
    }
}

// ---------------- GEMM split-K (atomic): C += alpha * A^T * B ; A[Ktot x M] rm --
__global__ void __launch_bounds__(256) gemm_atb_splitk_kernel(
    const float* __restrict__ A, const float* __restrict__ B, float* __restrict__ C,
    int M, int N, int Kchunk, float alpha)
{
    __shared__ float As[16][68];
    __shared__ float Bs[16][64];
    int tid = threadIdx.x;
    int n0 = blockIdx.x * 64, m0 = blockIdx.y * 64;
    int kbase = blockIdx.z * Kchunk;
    int tx = tid & 15, ty = tid >> 4;
    float acc[4][4] = {};

    for (int k0 = 0; k0 < Kchunk; k0 += 16) {
        #pragma unroll
        for (int l = 0; l < 4; l++) {
            int lin = tid + l * 256;
            int m = lin & 63, kk = lin >> 6;
            As[kk][m] = A[(size_t)(kbase + k0 + kk) * M + m0 + m];
            Bs[kk][m] = B[(size_t)(kbase + k0 + kk) * N + n0 + m];
        }
        __syncthreads();
        #pragma unroll
        for (int kk = 0; kk < 16; kk++) {
            float4 a = *(const float4*)&As[kk][ty * 4];
            float4 bv = *(const float4*)&Bs[kk][tx * 4];
            float av[4] = {a.x, a.y, a.z, a.w};
            float bb[4] = {bv.x, bv.y, bv.z, bv.w};
            #pragma unroll
            for (int i = 0; i < 4; i++)
                #pragma unroll
                for (int j = 0; j < 4; j++) acc[i][j] += av[i] * bb[j];
        }
        __syncthreads();
    }
    #pragma unroll
    for (int i = 0; i < 4; i++) {
        int m = m0 + ty * 4 + i;
        #pragma unroll
        for (int j = 0; j < 4; j++) {
            int n = n0 + tx * 4 + j;
            atomicAdd(&C[(size_t)m * N + n], alpha * acc[i][j]);
        }
    }
}

// ---------------- kernel: squash 32-vectors of s -> v ----------------
__global__ void squash_v_kernel() {
    int gid = blockIdx.x * blockDim.x + threadIdx.x;
    int warp = gid >> 5;                 // one warp per (b, o)
    int lane = gid & 31;
    if (warp >= BATCH * 2) return;
    int b = warp >> 1, o = warp & 1;
    float x = g_s[b * 64 + o * 32 + lane];
    float sq = warp_sum(x * x);
    float sc = sq / ((1.0f + sq) * sqrtf(sq + 1e-9f));
    g_v[b * 64 + o * 32 + lane] = x * sc;
}

// ---------------- kernel: b_ij update ----------------
__global__ void b_update_kernel(const float* __restrict__ W) {
    int gid = blockIdx.x * blockDim.x + threadIdx.x;
    int warp = gid >> 5;                 // one warp per (r, o), 1024 total
    int lane = gid & 31;
    if (warp >= NR * 2) return;
    int r = warp >> 1, o = warp & 1;
    float sum = 0.0f;
    for (int t = lane; t < 256; t += 32) {
        int d = t >> 3, i = t & 7;
        sum += W[(r * 2 + o) * 256 + t] * g_G[(r * 8 + i) * 64 + o * 32 + d];
    }
    sum = warp_sum(sum);
    if (lane == 0) g_bij[r * 2 + o] += sum;
}

// ---------------- kernel: mask / argmax / output write ----------------
__global__ void mask_kernel(float* __restrict__ out) {
    int gid = blockIdx.x * blockDim.x + threadIdx.x;
    int b = gid >> 5;                   // one warp per image
    int lane = gid & 31;
    if (b >= BATCH) return;
    float v0 = g_v[b * 64 + lane];
    float v1 = g_v[b * 64 + 32 + lane];
    float n0 = warp_sum(v0 * v0);
    float n1 = warp_sum(v1 * v1);
    // sqrt + softmax monotonic; jnp.argmax first-on-tie -> strict >
    int idx = (n1 > n0) ? 1 : 0;
    float m0 = (idx == 0) ? 1.0f : 0.0f;
    float m1 = 1.0f - m0;
    out[OUT_V_OFF + b * 64 + lane]       = v0;
    out[OUT_V_OFF + b * 64 + 32 + lane]  = v1;
    if (lane == 0) {
        out[OUT_MASK_OFF + b * 2 + 0] = m0;
        out[OUT_MASK_OFF + b * 2 + 1] = m1;
    }
    g_h0[b * 64 + lane]      = v0 * m0;
    g_h0[b * 64 + 32 + lane] = v1 * m1;
}

// ---------------- launch ----------------
extern "C" void kernel_launch(void* const* d_in, const int* in_sizes, int n_in,
                              void* d_out, int out_size)
{
    const float* data    = (const float*)d_in[0];
    const float* conv1_w = (const float*)d_in[1];
    const float* conv1_b = (const float*)d_in[2];
    const float* prim_w  = (const float*)d_in[3];
    const float* prim_b  = (const float*)d_in[4];
    const float* W_digit = (const float*)d_in[5];
    const float* dec1_w  = (const float*)d_in[6];
    const float* dec1_b  = (const float*)d_in[7];
    const float* dec2_w  = (const float*)d_in[8];
    const float* dec2_b  = (const float*)d_in[9];
    const float* dec3_w  = (const float*)d_in[10];
    const float* dec3_b  = (const float*)d_in[11];
    float* out = (float*)d_out;

    float *p_bij, *p_s, *p_G, *p_u, *p_WcT, *p_v, *p_h0, *p_h1, *p_h2;
    cudaGetSymbolAddress((void**)&p_bij, g_bij);
    cudaGetSymbolAddress((void**)&p_s,   g_s);
    cudaGetSymbolAddress((void**)&p_G,   g_G);
    cudaGetSymbolAddress((void**)&p_u,   g_u);
    cudaGetSymbolAddress((void**)&p_WcT, g_WcT);
    cudaGetSymbolAddress((void**)&p_v,   g_v);
    cudaGetSymbolAddress((void**)&p_h0,  g_h0);
    cudaGetSymbolAddress((void**)&p_h1,  g_h1);
    cudaGetSymbolAddress((void**)&p_h2,  g_h2);

    // one-time prep (deterministic; re-run every call)
    transpose_w_kernel<<<576, 256>>>(prim_w);
    zero_kernel<<<4, 256>>>(p_bij, NR * 2);

    // fused conv1 + primary caps + squash  -> g_u
    conv_fused_kernel<<<BATCH, 256>>>(data, conv1_w, conv1_b, prim_b);

    // dynamic routing, 3 iterations
    for (int it = 0; it < 3; it++) {
        softmax_routes_kernel<<<1, 512>>>();
        build_wct_kernel<<<1024, 256>>>(W_digit);
        zero_kernel<<<1024, 256>>>(p_s, BATCH * 64);
        gemm_ab_splitk_kernel<<<dim3(1, 64, 4), 256>>>(p_u, p_WcT, p_s,
                                                       BATCH, 64, RI, 1024);
        squash_v_kernel<<<1024, 256>>>();
        if (it < 2) {
            zero_kernel<<<1024, 256>>>(p_G, RI * 64);
            gemm_atb_splitk_kernel<<<dim3(1, 64, 8), 256>>>(p_u, p_v, p_G,
                                                            RI, 64, 512,
                                                            1.0f / (float)BATCH);
            b_update_kernel<<<128, 256>>>(W_digit);
        }
    }

    // mask + write v/masked outputs + build decoder input
    mask_kernel<<<512, 256>>>(out);

    // decoder
    gemm_ab_kernel<<<dim3(8, 64), 256>>>(p_h0, dec1_w, dec1_b, p_h1,
                                         BATCH, 512, 64, 1);
    gemm_ab_kernel<<<dim3(16, 64), 256>>>(p_h1, dec2_w, dec2_b, p_h2,
                                          BATCH, 1024, 512, 1);
    gemm_ab_kernel<<<dim3(1, 64), 256>>>(p_h2, dec3_w, dec3_b, out + OUT_REC_OFF,
                                         BATCH, 64, 1024, 2);
}